// round 11
// baseline (speedup 1.0000x reference)
#include <cuda_runtime.h>
#include <cstdint>

typedef unsigned long long u64;

#define N_ACT 80
#define M_CON 85
#define NP1   81
#define PDHG_ITERS 200
#define POWER_ITERS 20

// ---- packed f32x2 helpers ----
static __device__ __forceinline__ u64 pk(float lo, float hi) {
    u64 r; asm("mov.b64 %0, {%1, %2};" : "=l"(r) : "f"(lo), "f"(hi)); return r;
}
static __device__ __forceinline__ float2 up(u64 v) {
    float2 f; asm("mov.b64 {%0, %1}, %2;" : "=f"(f.x), "=f"(f.y) : "l"(v)); return f;
}
static __device__ __forceinline__ u64 ff2(u64 a, u64 b, u64 c) {
    u64 r; asm("fma.rn.f32x2 %0, %1, %2, %3;" : "=l"(r) : "l"(a), "l"(b), "l"(c)); return r;
}
static __device__ __forceinline__ u64 add2(u64 a, u64 b) {
    u64 r; asm("add.rn.f32x2 %0, %1, %2;" : "=l"(r) : "l"(a), "l"(b)); return r;
}

// Interleaved vector layout: logical j (0..87) -> physical float index.
// Halves interleave per 16B line: [h0_line0 | h1_line0 | h0_line1 | h1_line1 | ...]
// so a lane-pair's two LDS.128 addresses land in the same 32B (one L1 sector).
static __device__ __forceinline__ int perm(int j) {
    int half = (j >= 44);
    int jj = j - 44 * half;
    return 8 * (jj >> 2) + 4 * half + (jj & 3);
}

__device__ __forceinline__ float warp_sum(float v) {
    #pragma unroll
    for (int off = 16; off > 0; off >>= 1)
        v += __shfl_xor_sync(0xffffffffu, v, off);
    return v;
}
__device__ __forceinline__ float warp_min(float v) {
    #pragma unroll
    for (int off = 16; off > 0; off >>= 1)
        v = fminf(v, __shfl_xor_sync(0xffffffffu, v, off));
    return v;
}

// 44-float packed dot against the interleaved layout.
// base_v2 = (ulonglong2*)vec + part; the thread's 11 lines are base_v2[0,2,4,...,20].
__device__ __forceinline__ float dot44(const u64* __restrict__ G,
                                       const ulonglong2* __restrict__ base_v2) {
    u64 a0 = 0, a1 = 0, a2 = 0, a3 = 0;
    #pragma unroll
    for (int l = 0; l < 10; l += 2) {
        ulonglong2 pa = base_v2[2*l];
        ulonglong2 pb = base_v2[2*l + 2];
        a0 = ff2(G[2*l + 0], pa.x, a0);
        a1 = ff2(G[2*l + 1], pa.y, a1);
        a2 = ff2(G[2*l + 2], pb.x, a2);
        a3 = ff2(G[2*l + 3], pb.y, a3);
    }
    ulonglong2 pt = base_v2[20];
    a0 = ff2(G[20], pt.x, a0);
    a1 = ff2(G[21], pt.y, a1);
    u64 s = add2(add2(a0, a1), add2(a2, a3));
    float2 f = up(s);
    return f.x + f.y;
}

__global__ __launch_bounds__(256, 2)
void acp_kernel(const float* __restrict__ xhat,
                const float* __restrict__ Aglob,
                const float* __restrict__ bglob,
                float* __restrict__ out)
{
    // All vectors: 88 floats, INTERLEAVED layout, pads are hard zeros.
    __shared__ __align__(16) float sh_vec[88];   // v / z_bar (logical 0..80)
    __shared__ __align__(16) float sh_y[88];     // Gv / y    (logical 0..84)
    __shared__ __align__(16) float sh_x0[88];    // x0        (logical 0..79)
    __shared__ __align__(16) float sh_dv[88];    // x_hat-x0  (logical 0..79)
    __shared__ __align__(16) float sh_d[88];     // row norms (logical 0..84)
    __shared__ float sh_red[8];
    __shared__ float As[M_CON * 81];             // pitch 81 (unpermuted)

    const int t    = threadIdx.x;        // 0..255
    const int lane = t & 31;
    const int wid  = t >> 5;             // 0..7
    const int part = lane & 1;           // pair = lanes (2k, 2k+1)
    const int idx  = (lane >> 1) * 8 + wid;   // 0..127, interleaved over warps
    const bool rowAct = (idx < M_CON);
    const bool colAct = (idx < NP1);
    const int prob = blockIdx.x;

    // ---- stage A into shared (coalesced) ----
    {
        const float* Ap = Aglob + (size_t)prob * (M_CON * N_ACT);
        for (int i = t; i < M_CON * N_ACT; i += 256) {
            int rr = i / N_ACT;
            int cc = i - rr * N_ACT;
            As[rr * 81 + cc] = Ap[i];
        }
    }
    if (t < 88) {
        sh_y[t]  = 0.0f;
        sh_vec[perm(t)] = (t < NP1) ? 1.0f : 0.0f;   // power-iter v0 = ones
        sh_x0[t] = 0.0f;
        sh_dv[t] = 0.0f;
        sh_d[t]  = 0.0f;
    }
    __syncthreads();

    // ---- per-thread packed halves (registers are logical-ordered) ----
    u64 RP[22];        // row half: part0 = A[idx][0..43]; part1 = A[idx][44..79], slot80=d
    u64 CP[22];        // col half: part p = G[44p .. 44p+43][idx] (zeros past 84)
    float bval = 0.0f;

    #pragma unroll
    for (int k = 0; k < 22; k++) { RP[k] = 0; CP[k] = 0; }

    // row fill + norm (shfl hoisted to warp scope)
    {
        float ss = 0.0f;
        if (rowAct) {
            const float* Ar = &As[idx * 81];
            if (part == 0) {
                #pragma unroll
                for (int k = 0; k < 22; k++) {
                    float lo = Ar[2*k], hi = Ar[2*k + 1];
                    RP[k] = pk(lo, hi);
                    ss = fmaf(lo, lo, fmaf(hi, hi, ss));
                }
            } else {
                #pragma unroll
                for (int k = 0; k < 18; k++) {
                    float lo = Ar[44 + 2*k], hi = Ar[45 + 2*k];
                    RP[k] = pk(lo, hi);
                    ss = fmaf(lo, lo, fmaf(hi, hi, ss));
                }
            }
        }
        float tot = ss + __shfl_xor_sync(0xffffffffu, ss, 1);
        if (rowAct) {
            float dval = fmaxf(sqrtf(tot), 1e-12f);
            if (part == 1) RP[18] = pk(dval, 0.0f);   // logical element 80 of row-G
            if (part == 0) sh_d[perm(idx)] = dval;
            bval = bglob[(size_t)prob * M_CON + idx];
        }
    }
    __syncthreads();                       // sh_d complete (pads still zero)

    // col fill
    if (colAct) {
        if (idx < N_ACT) {
            if (part == 0) {
                #pragma unroll
                for (int k = 0; k < 22; k++)
                    CP[k] = pk(As[(2*k) * 81 + idx], As[(2*k + 1) * 81 + idx]);
            } else {
                #pragma unroll
                for (int k = 0; k < 20; k++)
                    CP[k] = pk(As[(44 + 2*k) * 81 + idx], As[(45 + 2*k) * 81 + idx]);
                CP[20] = pk(As[84 * 81 + idx], 0.0f);  // logical 84 (+ zero)
            }
        } else {   // idx == 80: column is d (read permuted sh_d by logical index)
            #pragma unroll
            for (int k = 0; k < 22; k++)
                CP[k] = pk(sh_d[perm(44 * part + 2*k)], sh_d[perm(44 * part + 2*k + 1)]);
        }
    }

    const ulonglong2* vecV = reinterpret_cast<const ulonglong2*>(sh_vec) + part;
    const ulonglong2* yV   = reinterpret_cast<const ulonglong2*>(sh_y)   + part;

    // ---- power iteration: v <- GT(G v), normalize every 3rd iter + last ----
    for (int pi = 0; pi < POWER_ITERS; pi++) {
        float pr = dot44(RP, vecV);                     // zero for inactive
        float g  = pr + __shfl_xor_sync(0xffffffffu, pr, 1);
        if (rowAct && part == 0) sh_y[perm(idx)] = g;
        __syncthreads();
        float pc = dot44(CP, yV);
        float w  = pc + __shfl_xor_sync(0xffffffffu, pc, 1);
        const bool norm_now = ((pi % 3) == 2) || (pi == POWER_ITERS - 1);
        if (norm_now) {
            float ss = warp_sum((colAct && part == 0) ? w * w : 0.0f);
            if (lane == 0) sh_red[wid] = ss;
            __syncthreads();
            float nrm = sqrtf(((sh_red[0] + sh_red[1]) + (sh_red[2] + sh_red[3])) +
                              ((sh_red[4] + sh_red[5]) + (sh_red[6] + sh_red[7]))) + 1e-12f;
            if (colAct && part == 0) sh_vec[perm(idx)] = w / nrm;
        } else {
            if (colAct && part == 0) sh_vec[perm(idx)] = w;
        }
        __syncthreads();
    }
    // L = ||G v||
    {
        float pr = dot44(RP, vecV);
        float g  = pr + __shfl_xor_sync(0xffffffffu, pr, 1);
        float ss = warp_sum((rowAct && part == 0) ? g * g : 0.0f);
        if (lane == 0) sh_red[wid] = ss;
        __syncthreads();
    }
    const float Lnrm = sqrtf(((sh_red[0] + sh_red[1]) + (sh_red[2] + sh_red[3])) +
                             ((sh_red[4] + sh_red[5]) + (sh_red[6] + sh_red[7])));
    const float tau  = 0.9f / fmaxf(Lnrm, 1e-6f);       // sigma == tau

    // ---- PDHG: 200 fixed iterations ----
    if (t < 88) sh_y[t] = 0.0f;
    float zv = 0.0f, yv = 0.0f;
    const float cterm = (idx == N_ACT) ? -1.0f : 0.0f;
    __syncthreads();

    for (int it = 0; it < PDHG_ITERS; it++) {
        float pc  = dot44(CP, yV);
        float gty = pc + __shfl_xor_sync(0xffffffffu, pc, 1);
        float znew = fmaxf(zv - tau * (cterm + gty), 0.0f);
        if (colAct && part == 0) sh_vec[perm(idx)] = 2.0f * znew - zv;   // z_bar
        zv = znew;
        __syncthreads();
        float pr = dot44(RP, vecV);
        float gz = pr + __shfl_xor_sync(0xffffffffu, pr, 1);
        yv = fmaxf(yv + tau * (gz - bval), 0.0f);
        if (rowAct && part == 0) sh_y[perm(idx)] = yv;
        __syncthreads();
    }

    // ---- alpha map ----
    if (idx < N_ACT && part == 0) {
        sh_x0[perm(idx)] = zv;
        sh_dv[perm(idx)] = xhat[(size_t)prob * N_ACT + idx] - zv;
    }
    __syncthreads();

    const float INF = __int_as_float(0x7f800000);
    float ai;
    {
        // sh_x0/sh_dv pads (incl. logical 80) are zero -> RP's dval term vanishes.
        const ulonglong2* x0V = reinterpret_cast<const ulonglong2*>(sh_x0) + part;
        const ulonglong2* dvV = reinterpret_cast<const ulonglong2*>(sh_dv) + part;
        float p0 = dot44(RP, x0V);
        float p1 = dot44(RP, dvV);
        float ax0 = p0 + __shfl_xor_sync(0xffffffffu, p0, 1);
        float ad  = p1 + __shfl_xor_sync(0xffffffffu, p1, 1);
        if (rowAct) {
            float slack = fmaxf(bval - ax0, 0.0f);
            ai = (ad > 0.0f) ? (slack / (ad + 1e-12f)) : INF;
        } else {
            ai = INF;
        }
    }
    ai = warp_min(ai);
    if (lane == 0) sh_red[wid] = ai;
    __syncthreads();
    float alpha = fminf(fminf(fminf(sh_red[0], sh_red[1]), fminf(sh_red[2], sh_red[3])),
                        fminf(fminf(sh_red[4], sh_red[5]), fminf(sh_red[6], sh_red[7])));
    if (!isfinite(alpha)) alpha = 1.0f;
    alpha = fminf(fmaxf(alpha - 1e-9f, 0.0f), 1.0f);

    if (idx < N_ACT && part == 0)
        out[(size_t)prob * N_ACT + idx] =
            fmaxf(sh_x0[perm(idx)] + alpha * sh_dv[perm(idx)], 0.0f);
}

extern "C" void kernel_launch(void* const* d_in, const int* in_sizes, int n_in,
                              void* d_out, int out_size)
{
    const float* xhat = (const float*)d_in[0];
    const float* A    = (const float*)d_in[1];
    const float* b    = (const float*)d_in[2];
    float* out        = (float*)d_out;
    int P = in_sizes[0] / N_ACT;     // 1024 problems
    acp_kernel<<<P, 256>>>(xhat, A, b, out);
}